// round 12
// baseline (speedup 1.0000x reference)
#include <cuda_runtime.h>
#include <cuda_bf16.h>
#include <math.h>
#include <stdint.h>

// ---------------- problem constants ----------------
#define TOK   32768      // B*H*W tokens
#define CD    512        // channels
#define HWD   1024       // H*W per batch
#define NHEAD 16
#define HD    32
#define NWIN  2048       // B * 64 windows
#define QSTR2 1544       // bf16 elements per staged qkv row (1536 + 8)
#define SSTR  40         // smem row stride in bf16 (32 data + 8 pad) -> 80B, ldmatrix conflict-free
#define STAGEB 20480     // bytes per pipeline stage (A 10240 + B 10240)
#define GSMEM  (3 * STAGEB)   // 61440 B dynamic smem for gemm

// ---------------- scratch (__device__ globals, no allocation) ----------------
__device__ __align__(16) float         g_xh  [TOK * CD];     // residual 1 (fp32)
__device__ __align__(16) float         g_x2  [TOK * CD];     // residual 2 (fp32)
__device__ __align__(16) __nv_bfloat16 g_xnb [TOK * CD];     // LN1 out bf16
__device__ __align__(16) __nv_bfloat16 g_qkvb[TOK * 1536];   // qkv bf16
__device__ __align__(16) __nv_bfloat16 g_attb[TOK * CD];     // attention out bf16
__device__ __align__(16) __nv_bfloat16 g_yb  [TOK * CD];     // LN2 out bf16
__device__ __align__(16) __nv_bfloat16 g_h1b [TOK * 2048];   // MLP hidden bf16
__device__ __align__(16) __nv_bfloat16 g_wqkv[1536 * 512];
__device__ __align__(16) __nv_bfloat16 g_wprj[512 * 512];
__device__ __align__(16) __nv_bfloat16 g_w1  [2048 * 512];
__device__ __align__(16) __nv_bfloat16 g_w2  [512 * 2048];

// ---------------- PTX helpers (portable sm_80+ only) ----------------
__device__ __forceinline__ uint32_t smem_u32(const void* p) {
    uint32_t a;
    asm("{ .reg .u64 t; cvta.to.shared.u64 t, %1; cvt.u32.u64 %0, t; }" : "=r"(a) : "l"(p));
    return a;
}
__device__ __forceinline__ void ldsm_x4(uint32_t* r, uint32_t addr) {
    asm volatile("ldmatrix.sync.aligned.m8n8.x4.shared.b16 {%0,%1,%2,%3}, [%4];"
        : "=r"(r[0]), "=r"(r[1]), "=r"(r[2]), "=r"(r[3]) : "r"(addr));
}
__device__ __forceinline__ void mma_bf16(float* d, const uint32_t* a, const uint32_t* b) {
    asm volatile("mma.sync.aligned.m16n8k16.row.col.f32.bf16.bf16.f32 "
        "{%0,%1,%2,%3}, {%4,%5,%6,%7}, {%8,%9}, {%0,%1,%2,%3};"
        : "+f"(d[0]), "+f"(d[1]), "+f"(d[2]), "+f"(d[3])
        : "r"(a[0]), "r"(a[1]), "r"(a[2]), "r"(a[3]), "r"(b[0]), "r"(b[1]));
}
__device__ __forceinline__ void cp_async16(uint32_t dst, const void* src) {
    asm volatile("cp.async.cg.shared.global [%0], [%1], 16;" :: "r"(dst), "l"(src));
}
#define CP_COMMIT() asm volatile("cp.async.commit_group;" ::: "memory")
#define CP_WAIT(n)  asm volatile("cp.async.wait_group %0;" :: "n"(n) : "memory")

// ---------------- transpose in ----------------
__global__ void transpose_in(const float* __restrict__ x, float* __restrict__ xh) {
    __shared__ float tile[32][33];
    int b = blockIdx.z, c0 = blockIdx.y * 32, p0 = blockIdx.x * 32;
    int tx = threadIdx.x, ty = threadIdx.y;
    #pragma unroll
    for (int i = 0; i < 32; i += 8)
        tile[ty + i][tx] = x[((size_t)b * CD + c0 + ty + i) * HWD + p0 + tx];
    __syncthreads();
    #pragma unroll
    for (int i = 0; i < 32; i += 8)
        xh[((size_t)b * HWD + p0 + ty + i) * CD + c0 + tx] = tile[tx][ty + i];
}

// ---------------- weight fp32 -> bf16 ----------------
__global__ void wcvt(const float* __restrict__ s, __nv_bfloat16* __restrict__ d, int n) {
    int i = blockIdx.x * 256 + threadIdx.x;
    if (i < n) d[i] = __float2bfloat16(s[i]);
}

// ---------------- LayerNorm (fp32 in -> bf16 out) ----------------
__global__ void __launch_bounds__(256) ln_kernel(const float* __restrict__ in,
        const float* __restrict__ w, const float* __restrict__ b,
        __nv_bfloat16* __restrict__ out) {
    int row  = blockIdx.x * 8 + (threadIdx.x >> 5);
    int lane = threadIdx.x & 31;
    const float4* p = (const float4*)(in + (size_t)row * CD);
    float4 v[4];
    float s = 0.f, s2 = 0.f;
    #pragma unroll
    for (int j = 0; j < 4; j++) {
        v[j] = p[lane + 32 * j];
        s  += v[j].x + v[j].y + v[j].z + v[j].w;
        s2 += v[j].x * v[j].x + v[j].y * v[j].y + v[j].z * v[j].z + v[j].w * v[j].w;
    }
    #pragma unroll
    for (int o = 16; o > 0; o >>= 1) {
        s  += __shfl_xor_sync(0xffffffffu, s,  o);
        s2 += __shfl_xor_sync(0xffffffffu, s2, o);
    }
    float mean = s * (1.f / CD);
    float var  = s2 * (1.f / CD) - mean * mean;
    float rstd = rsqrtf(var + 1e-5f);
    __nv_bfloat16* q = out + (size_t)row * CD;
    const float4* wp = (const float4*)w;
    const float4* bp = (const float4*)b;
    #pragma unroll
    for (int j = 0; j < 4; j++) {
        int c4 = lane + 32 * j;
        float4 wv = wp[c4], bv = bp[c4], x = v[j];
        float ox = (x.x - mean) * rstd * wv.x + bv.x;
        float oy = (x.y - mean) * rstd * wv.y + bv.y;
        float oz = (x.z - mean) * rstd * wv.z + bv.z;
        float ow = (x.w - mean) * rstd * wv.w + bv.w;
        *(__nv_bfloat162*)(q + c4 * 4)     = __floats2bfloat162_rn(ox, oy);
        *(__nv_bfloat162*)(q + c4 * 4 + 2) = __floats2bfloat162_rn(oz, ow);
    }
}

// ---------------- mma.sync bf16 GEMM: C = A[M,K] * W[N,K]^T + bias (+epi) -----
// Block 128x128, 8 warps (2x4), warp tile 64x32, K-chunks of 32, 3-stage cp.async.
// EPI: 0 bf16 out; 1 gelu->bf16; 2 +fp32 residual->fp32; 3 +fp32 residual -> [B,C,HW] fp32.
__device__ __forceinline__ float gelu_exact(float v) {
    return 0.5f * v * (1.f + erff(v * 0.70710678118654752f));
}

template <int EPI>
__global__ void __launch_bounds__(256, 2) gemm_mma(
        const __nv_bfloat16* __restrict__ A, const __nv_bfloat16* __restrict__ Wt,
        const float* __restrict__ bias, const float* __restrict__ res,
        void* __restrict__ Cout, int M, int N, int K) {
    extern __shared__ __align__(16) char smem[];
    const int tid = threadIdx.x, wid = tid >> 5, lane = tid & 31;
    const int bm = blockIdx.y * 128, bn = blockIdx.x * 128;
    const int wm = (wid >> 2) * 64, wn = (wid & 3) * 32;
    const uint32_t sb = smem_u32(smem);

    float acc[4][4][4];
    #pragma unroll
    for (int i = 0; i < 4; i++)
        #pragma unroll
        for (int j = 0; j < 4; j++)
            #pragma unroll
            for (int q = 0; q < 4; q++) acc[i][j][q] = 0.f;

    const int NC = K >> 5;   // >= 16 always here

    auto issue = [&](int stg, int k0) {
        uint32_t base = sb + stg * STAGEB;
        #pragma unroll
        for (int i = 0; i < 4; i++) {
            int u = tid + i * 256;
            if (u < 512) {
                int r = u >> 2, q = u & 3;
                cp_async16(base + (uint32_t)(r * SSTR + q * 8) * 2,
                           A + (size_t)(bm + r) * K + k0 + q * 8);
            } else {
                int v = u - 512, r = v >> 2, q = v & 3;
                cp_async16(base + 10240 + (uint32_t)(r * SSTR + q * 8) * 2,
                           Wt + (size_t)(bn + r) * K + k0 + q * 8);
            }
        }
        CP_COMMIT();
    };

    issue(0, 0);
    issue(1, 32);
    int stg = 0;
    for (int c = 0; c < NC; c++) {
        if (c + 2 < NC) issue((stg + 2) % 3, (c + 2) * 32);
        else            CP_COMMIT();          // empty group keeps wait arithmetic uniform
        CP_WAIT(2);
        __syncthreads();
        const uint32_t Ab = sb + stg * STAGEB;
        const uint32_t Bb = Ab + 10240;
        #pragma unroll
        for (int kk = 0; kk < 2; kk++) {
            uint32_t a[4][4], b[4][2];
            #pragma unroll
            for (int mi = 0; mi < 4; mi++) {
                uint32_t row = wm + mi * 16 + (lane & 15);
                uint32_t kb  = kk * 32 + (lane >> 4) * 16;       // bytes
                ldsm_x4(a[mi], Ab + row * (SSTR * 2) + kb);
            }
            #pragma unroll
            for (int nh = 0; nh < 2; nh++) {
                uint32_t r4[4];
                uint32_t nrow = wn + nh * 16 + (lane & 7) + ((lane >> 4) << 3);
                uint32_t kb   = kk * 32 + ((lane >> 3) & 1) * 16;
                ldsm_x4(r4, Bb + nrow * (SSTR * 2) + kb);
                b[nh * 2 + 0][0] = r4[0]; b[nh * 2 + 0][1] = r4[1];
                b[nh * 2 + 1][0] = r4[2]; b[nh * 2 + 1][1] = r4[3];
            }
            #pragma unroll
            for (int mi = 0; mi < 4; mi++)
                #pragma unroll
                for (int ni = 0; ni < 4; ni++)
                    mma_bf16(acc[mi][ni], a[mi], b[ni]);
        }
        __syncthreads();
        stg = (stg + 1) % 3;
    }
    CP_WAIT(0);

    if (EPI == 3) {
        // residual add + transpose to [B,C,HW] via smem slices (reuse pipeline smem)
        float* sT = (float*)smem;               // [32 ch][129 tok] fp32 = 16512 B
        const int b  = bm >> 10;                // HWD = 1024 tokens per batch
        const int p0 = bm & 1023;
        float* outp = (float*)Cout;
        #pragma unroll 1
        for (int s4 = 0; s4 < 4; s4++) {
            __syncthreads();
            if ((wid & 3) == s4) {              // warps owning cols [32*s4, 32*s4+32)
                #pragma unroll
                for (int mi = 0; mi < 4; mi++)
                    #pragma unroll
                    for (int half = 0; half < 2; half++) {
                        int ml = wm + mi * 16 + (lane >> 2) + half * 8;
                        #pragma unroll
                        for (int ni = 0; ni < 4; ni++) {
                            int nl = ni * 8 + (lane & 3) * 2;      // 0..31 within slice
                            int ng = bn + s4 * 32 + nl;
                            float2 bv = *(const float2*)(bias + ng);
                            float2 rv = *(const float2*)(res + (size_t)(bm + ml) * N + ng);
                            sT[nl * 129 + ml]       = acc[mi][ni][half * 2 + 0] + bv.x + rv.x;
                            sT[(nl + 1) * 129 + ml] = acc[mi][ni][half * 2 + 1] + bv.y + rv.y;
                        }
                    }
            }
            __syncthreads();
            #pragma unroll
            for (int u = tid; u < 32 * 128; u += 256) {
                int cc = u >> 7, pp = u & 127;
                outp[((size_t)b * CD + bn + s4 * 32 + cc) * HWD + p0 + pp] = sT[cc * 129 + pp];
            }
        }
        return;
    }

    #pragma unroll
    for (int mi = 0; mi < 4; mi++) {
        #pragma unroll
        for (int half = 0; half < 2; half++) {
            int m = bm + wm + mi * 16 + (lane >> 2) + half * 8;
            #pragma unroll
            for (int ni = 0; ni < 4; ni++) {
                int n = bn + wn + ni * 8 + (lane & 3) * 2;
                float2 bv = *(const float2*)(bias + n);
                float f0 = acc[mi][ni][half * 2 + 0] + bv.x;
                float f1 = acc[mi][ni][half * 2 + 1] + bv.y;
                if (EPI == 1) { f0 = gelu_exact(f0); f1 = gelu_exact(f1); }
                if (EPI == 2) {
                    float2 rv = *(const float2*)(res + (size_t)m * N + n);
                    *(float2*)((float*)Cout + (size_t)m * N + n) =
                        make_float2(f0 + rv.x, f1 + rv.y);
                } else {
                    *(__nv_bfloat162*)((__nv_bfloat16*)Cout + (size_t)m * N + n) =
                        __floats2bfloat162_rn(f0, f1);
                }
            }
        }
    }
}

// ---------------- windowed attention (bf16 in/out, fp32 math) ----------------
__global__ void __launch_bounds__(512) attn_kernel(const __nv_bfloat16* __restrict__ qkv,
        const float* __restrict__ rpb, __nv_bfloat16* __restrict__ O) {
    extern __shared__ char asmem[];
    __nv_bfloat16* sQ = (__nv_bfloat16*)asmem;           // 16 x QSTR2 bf16
    float* S = (float*)(asmem + 16 * QSTR2 * 2);         // 16 heads x 16 x 17
    const int w = blockIdx.x;
    const int b = w >> 6, wi = w & 63, wh = wi >> 3, ww = wi & 7;
    const int base = (b * 32 + wh * 4) * 32 + ww * 4;
    const int tid = threadIdx.x;

    for (int u = tid; u < 16 * 768; u += 512) {
        int i = u / 768; int c = u - i * 768;
        int t = base + (i >> 2) * 32 + (i & 3);
        ((uint32_t*)asmem)[i * 772 + c] = ((const uint32_t*)(qkv + (size_t)t * 1536))[c];
    }
    __syncthreads();

    const int head = tid >> 5, lane = tid & 31;
    float* Sh = S + head * 272;
    const float scale = 0.17677669529663689f;
    #pragma unroll
    for (int e = 0; e < 8; e++) {
        int idx = lane * 8 + e;
        int i = idx >> 4, j = idx & 15;
        const __nv_bfloat162* qp = (const __nv_bfloat162*)(sQ + i * QSTR2 + head * HD);
        const __nv_bfloat162* kp = (const __nv_bfloat162*)(sQ + j * QSTR2 + 512 + head * HD);
        float acc = 0.f;
        #pragma unroll
        for (int d = 0; d < 16; d++) {
            float2 qa = __bfloat1622float2(qp[d]);
            float2 kb = __bfloat1622float2(kp[d]);
            acc += qa.x * kb.x + qa.y * kb.y;
        }
        int ri = i >> 2, ci = i & 3, rj = j >> 2, cj = j & 3;
        int bidx = (ri - rj + 3) * 7 + (ci - cj + 3);
        Sh[i * 17 + j] = acc * scale + rpb[bidx * NHEAD + head];
    }
    __syncwarp();
    if (lane < 16) {
        float* row = Sh + lane * 17;
        float m = row[0];
        #pragma unroll
        for (int j = 1; j < 16; j++) m = fmaxf(m, row[j]);
        float s = 0.f;
        #pragma unroll
        for (int j = 0; j < 16; j++) { float e = __expf(row[j] - m); row[j] = e; s += e; }
        float inv = 1.f / s;
        #pragma unroll
        for (int j = 0; j < 16; j++) row[j] *= inv;
    }
    __syncwarp();
    #pragma unroll
    for (int i = 0; i < 16; i++) {
        float acc = 0.f;
        #pragma unroll
        for (int j = 0; j < 16; j++)
            acc += Sh[i * 17 + j] * __bfloat162float(sQ[j * QSTR2 + 1024 + head * HD + lane]);
        int t = base + (i >> 2) * 32 + (i & 3);
        O[(size_t)t * CD + head * HD + lane] = __float2bfloat16(acc);
    }
}

// ---------------- launch ----------------
extern "C" void kernel_launch(void* const* d_in, const int* in_sizes, int n_in,
                              void* d_out, int out_size) {
    const float* x      = (const float*)d_in[0];
    const float* n1w    = (const float*)d_in[1];
    const float* n1b    = (const float*)d_in[2];
    const float* qkv_w  = (const float*)d_in[3];
    const float* qkv_b  = (const float*)d_in[4];
    const float* rpb    = (const float*)d_in[5];
    const float* proj_w = (const float*)d_in[6];
    const float* proj_b = (const float*)d_in[7];
    const float* n2w    = (const float*)d_in[8];
    const float* n2b    = (const float*)d_in[9];
    const float* w1     = (const float*)d_in[10];
    const float* b1     = (const float*)d_in[11];
    const float* w2     = (const float*)d_in[12];
    const float* b2     = (const float*)d_in[13];
    float* out = (float*)d_out;

    float *xh, *x2;
    __nv_bfloat16 *xnb, *qkvb, *attb, *yb, *h1b, *wqkv, *wprj, *w1b, *w2b;
    cudaGetSymbolAddress((void**)&xh,   g_xh);
    cudaGetSymbolAddress((void**)&x2,   g_x2);
    cudaGetSymbolAddress((void**)&xnb,  g_xnb);
    cudaGetSymbolAddress((void**)&qkvb, g_qkvb);
    cudaGetSymbolAddress((void**)&attb, g_attb);
    cudaGetSymbolAddress((void**)&yb,   g_yb);
    cudaGetSymbolAddress((void**)&h1b,  g_h1b);
    cudaGetSymbolAddress((void**)&wqkv, g_wqkv);
    cudaGetSymbolAddress((void**)&wprj, g_wprj);
    cudaGetSymbolAddress((void**)&w1b,  g_w1);
    cudaGetSymbolAddress((void**)&w2b,  g_w2);

    const int attn_smem = 16 * QSTR2 * 2 + 16 * 272 * 4;   // 66816 bytes
    cudaFuncSetAttribute(attn_kernel, cudaFuncAttributeMaxDynamicSharedMemorySize, attn_smem);
    cudaFuncSetAttribute(gemm_mma<0>, cudaFuncAttributeMaxDynamicSharedMemorySize, GSMEM);
    cudaFuncSetAttribute(gemm_mma<1>, cudaFuncAttributeMaxDynamicSharedMemorySize, GSMEM);
    cudaFuncSetAttribute(gemm_mma<2>, cudaFuncAttributeMaxDynamicSharedMemorySize, GSMEM);
    cudaFuncSetAttribute(gemm_mma<3>, cudaFuncAttributeMaxDynamicSharedMemorySize, GSMEM);

    dim3 tb(32, 8);
    transpose_in<<<dim3(32, 16, 32), tb>>>(x, xh);
    wcvt<<<(1536 * 512 + 255) / 256, 256>>>(qkv_w,  wqkv, 1536 * 512);
    wcvt<<<(512  * 512 + 255) / 256, 256>>>(proj_w, wprj, 512 * 512);
    wcvt<<<(2048 * 512 + 255) / 256, 256>>>(w1,     w1b,  2048 * 512);
    wcvt<<<(512 * 2048 + 255) / 256, 256>>>(w2,     w2b,  512 * 2048);

    ln_kernel<<<TOK / 8, 256>>>(xh, n1w, n1b, xnb);
    gemm_mma<0><<<dim3(12, 256), 256, GSMEM>>>(xnb, wqkv, qkv_b, nullptr, qkvb, TOK, 1536, 512);
    attn_kernel<<<NWIN, 512, attn_smem>>>(qkvb, rpb, attb);
    gemm_mma<2><<<dim3(4, 256), 256, GSMEM>>>(attb, wprj, proj_b, xh, x2, TOK, 512, 512);
    ln_kernel<<<TOK / 8, 256>>>(x2, n2w, n2b, yb);
    gemm_mma<1><<<dim3(16, 256), 256, GSMEM>>>(yb, w1b, b1, nullptr, h1b, TOK, 2048, 512);
    // fc2 + residual + fused transpose straight into [B,C,HW] output
    gemm_mma<3><<<dim3(4, 256), 256, GSMEM>>>(h1b, w2b, b2, x2, out, TOK, 512, 2048);
}

// round 14
// speedup vs baseline: 1.0375x; 1.0375x over previous
#include <cuda_runtime.h>
#include <cuda_bf16.h>
#include <math.h>
#include <stdint.h>

// ---------------- problem constants ----------------
#define TOK   32768      // B*H*W tokens
#define CD    512        // channels
#define HWD   1024       // H*W per batch
#define NHEAD 16
#define HD    32
#define NWIN  2048       // B * 64 windows
#define SSTR  40         // gemm smem row stride bf16 (32 data + 8 pad)
#define STAGEB 20480     // bytes per pipeline stage (A 10240 + B 10240)
#define GSMEM  (3 * STAGEB)
#define AQ    36         // attn per-warp qkv row stride in bf16 (72 B)

// ---------------- scratch (__device__ globals, no allocation) ----------------
__device__ __align__(16) float         g_xh  [TOK * CD];
__device__ __align__(16) float         g_x2  [TOK * CD];
__device__ __align__(16) __nv_bfloat16 g_xnb [TOK * CD];
__device__ __align__(16) __nv_bfloat16 g_qkvb[TOK * 1536];
__device__ __align__(16) __nv_bfloat16 g_attb[TOK * CD];
__device__ __align__(16) __nv_bfloat16 g_yb  [TOK * CD];
__device__ __align__(16) __nv_bfloat16 g_h1b [TOK * 2048];
__device__ __align__(16) __nv_bfloat16 g_wqkv[1536 * 512];
__device__ __align__(16) __nv_bfloat16 g_wprj[512 * 512];
__device__ __align__(16) __nv_bfloat16 g_w1  [2048 * 512];
__device__ __align__(16) __nv_bfloat16 g_w2  [512 * 2048];

// ---------------- PTX helpers (portable sm_80+ only) ----------------
__device__ __forceinline__ uint32_t smem_u32(const void* p) {
    uint32_t a;
    asm("{ .reg .u64 t; cvta.to.shared.u64 t, %1; cvt.u32.u64 %0, t; }" : "=r"(a) : "l"(p));
    return a;
}
__device__ __forceinline__ void ldsm_x4(uint32_t* r, uint32_t addr) {
    asm volatile("ldmatrix.sync.aligned.m8n8.x4.shared.b16 {%0,%1,%2,%3}, [%4];"
        : "=r"(r[0]), "=r"(r[1]), "=r"(r[2]), "=r"(r[3]) : "r"(addr));
}
__device__ __forceinline__ void mma_bf16(float* d, const uint32_t* a, const uint32_t* b) {
    asm volatile("mma.sync.aligned.m16n8k16.row.col.f32.bf16.bf16.f32 "
        "{%0,%1,%2,%3}, {%4,%5,%6,%7}, {%8,%9}, {%0,%1,%2,%3};"
        : "+f"(d[0]), "+f"(d[1]), "+f"(d[2]), "+f"(d[3])
        : "r"(a[0]), "r"(a[1]), "r"(a[2]), "r"(a[3]), "r"(b[0]), "r"(b[1]));
}
__device__ __forceinline__ void cp_async16(uint32_t dst, const void* src) {
    asm volatile("cp.async.cg.shared.global [%0], [%1], 16;" :: "r"(dst), "l"(src));
}
#define CP_COMMIT() asm volatile("cp.async.commit_group;" ::: "memory")
#define CP_WAIT(n)  asm volatile("cp.async.wait_group %0;" :: "n"(n) : "memory")

// ---------------- transpose in ----------------
__global__ void transpose_in(const float* __restrict__ x, float* __restrict__ xh) {
    __shared__ float tile[32][33];
    int b = blockIdx.z, c0 = blockIdx.y * 32, p0 = blockIdx.x * 32;
    int tx = threadIdx.x, ty = threadIdx.y;
    #pragma unroll
    for (int i = 0; i < 32; i += 8)
        tile[ty + i][tx] = x[((size_t)b * CD + c0 + ty + i) * HWD + p0 + tx];
    __syncthreads();
    #pragma unroll
    for (int i = 0; i < 32; i += 8)
        xh[((size_t)b * HWD + p0 + ty + i) * CD + c0 + tx] = tile[tx][ty + i];
}

// ---------------- weight fp32 -> bf16 ----------------
__global__ void wcvt(const float* __restrict__ s, __nv_bfloat16* __restrict__ d, int n) {
    int i = blockIdx.x * 256 + threadIdx.x;
    if (i < n) d[i] = __float2bfloat16(s[i]);
}

// ---------------- LayerNorm (fp32 in -> bf16 out) ----------------
__global__ void __launch_bounds__(256) ln_kernel(const float* __restrict__ in,
        const float* __restrict__ w, const float* __restrict__ b,
        __nv_bfloat16* __restrict__ out) {
    int row  = blockIdx.x * 8 + (threadIdx.x >> 5);
    int lane = threadIdx.x & 31;
    const float4* p = (const float4*)(in + (size_t)row * CD);
    float4 v[4];
    float s = 0.f, s2 = 0.f;
    #pragma unroll
    for (int j = 0; j < 4; j++) {
        v[j] = p[lane + 32 * j];
        s  += v[j].x + v[j].y + v[j].z + v[j].w;
        s2 += v[j].x * v[j].x + v[j].y * v[j].y + v[j].z * v[j].z + v[j].w * v[j].w;
    }
    #pragma unroll
    for (int o = 16; o > 0; o >>= 1) {
        s  += __shfl_xor_sync(0xffffffffu, s,  o);
        s2 += __shfl_xor_sync(0xffffffffu, s2, o);
    }
    float mean = s * (1.f / CD);
    float var  = s2 * (1.f / CD) - mean * mean;
    float rstd = rsqrtf(var + 1e-5f);
    __nv_bfloat16* q = out + (size_t)row * CD;
    const float4* wp = (const float4*)w;
    const float4* bp = (const float4*)b;
    #pragma unroll
    for (int j = 0; j < 4; j++) {
        int c4 = lane + 32 * j;
        float4 wv = wp[c4], bv = bp[c4], x = v[j];
        float ox = (x.x - mean) * rstd * wv.x + bv.x;
        float oy = (x.y - mean) * rstd * wv.y + bv.y;
        float oz = (x.z - mean) * rstd * wv.z + bv.z;
        float ow = (x.w - mean) * rstd * wv.w + bv.w;
        *(__nv_bfloat162*)(q + c4 * 4)     = __floats2bfloat162_rn(ox, oy);
        *(__nv_bfloat162*)(q + c4 * 4 + 2) = __floats2bfloat162_rn(oz, ow);
    }
}

// ---------------- mma.sync bf16 GEMM (unchanged from R12) --------------------
__device__ __forceinline__ float gelu_exact(float v) {
    return 0.5f * v * (1.f + erff(v * 0.70710678118654752f));
}

template <int EPI>
__global__ void __launch_bounds__(256, 2) gemm_mma(
        const __nv_bfloat16* __restrict__ A, const __nv_bfloat16* __restrict__ Wt,
        const float* __restrict__ bias, const float* __restrict__ res,
        void* __restrict__ Cout, int M, int N, int K) {
    extern __shared__ __align__(16) char smem[];
    const int tid = threadIdx.x, wid = tid >> 5, lane = tid & 31;
    const int bm = blockIdx.y * 128, bn = blockIdx.x * 128;
    const int wm = (wid >> 2) * 64, wn = (wid & 3) * 32;
    const uint32_t sb = smem_u32(smem);

    float acc[4][4][4];
    #pragma unroll
    for (int i = 0; i < 4; i++)
        #pragma unroll
        for (int j = 0; j < 4; j++)
            #pragma unroll
            for (int q = 0; q < 4; q++) acc[i][j][q] = 0.f;

    const int NC = K >> 5;

    auto issue = [&](int stg, int k0) {
        uint32_t base = sb + stg * STAGEB;
        #pragma unroll
        for (int i = 0; i < 4; i++) {
            int u = tid + i * 256;
            if (u < 512) {
                int r = u >> 2, q = u & 3;
                cp_async16(base + (uint32_t)(r * SSTR + q * 8) * 2,
                           A + (size_t)(bm + r) * K + k0 + q * 8);
            } else {
                int v = u - 512, r = v >> 2, q = v & 3;
                cp_async16(base + 10240 + (uint32_t)(r * SSTR + q * 8) * 2,
                           Wt + (size_t)(bn + r) * K + k0 + q * 8);
            }
        }
        CP_COMMIT();
    };

    issue(0, 0);
    issue(1, 32);
    int stg = 0;
    for (int c = 0; c < NC; c++) {
        if (c + 2 < NC) issue((stg + 2) % 3, (c + 2) * 32);
        else            CP_COMMIT();
        CP_WAIT(2);
        __syncthreads();
        const uint32_t Ab = sb + stg * STAGEB;
        const uint32_t Bb = Ab + 10240;
        #pragma unroll
        for (int kk = 0; kk < 2; kk++) {
            uint32_t a[4][4], b[4][2];
            #pragma unroll
            for (int mi = 0; mi < 4; mi++) {
                uint32_t row = wm + mi * 16 + (lane & 15);
                uint32_t kb  = kk * 32 + (lane >> 4) * 16;
                ldsm_x4(a[mi], Ab + row * (SSTR * 2) + kb);
            }
            #pragma unroll
            for (int nh = 0; nh < 2; nh++) {
                uint32_t r4[4];
                uint32_t nrow = wn + nh * 16 + (lane & 7) + ((lane >> 4) << 3);
                uint32_t kb   = kk * 32 + ((lane >> 3) & 1) * 16;
                ldsm_x4(r4, Bb + nrow * (SSTR * 2) + kb);
                b[nh * 2 + 0][0] = r4[0]; b[nh * 2 + 0][1] = r4[1];
                b[nh * 2 + 1][0] = r4[2]; b[nh * 2 + 1][1] = r4[3];
            }
            #pragma unroll
            for (int mi = 0; mi < 4; mi++)
                #pragma unroll
                for (int ni = 0; ni < 4; ni++)
                    mma_bf16(acc[mi][ni], a[mi], b[ni]);
        }
        __syncthreads();
        stg = (stg + 1) % 3;
    }
    CP_WAIT(0);

    if (EPI == 3) {
        float* sT = (float*)smem;
        const int b  = bm >> 10;
        const int p0 = bm & 1023;
        float* outp = (float*)Cout;
        #pragma unroll 1
        for (int s4 = 0; s4 < 4; s4++) {
            __syncthreads();
            if ((wid & 3) == s4) {
                #pragma unroll
                for (int mi = 0; mi < 4; mi++)
                    #pragma unroll
                    for (int half = 0; half < 2; half++) {
                        int ml = wm + mi * 16 + (lane >> 2) + half * 8;
                        #pragma unroll
                        for (int ni = 0; ni < 4; ni++) {
                            int nl = ni * 8 + (lane & 3) * 2;
                            int ng = bn + s4 * 32 + nl;
                            float2 bv = *(const float2*)(bias + ng);
                            float2 rv = *(const float2*)(res + (size_t)(bm + ml) * N + ng);
                            sT[nl * 129 + ml]       = acc[mi][ni][half * 2 + 0] + bv.x + rv.x;
                            sT[(nl + 1) * 129 + ml] = acc[mi][ni][half * 2 + 1] + bv.y + rv.y;
                        }
                    }
            }
            __syncthreads();
            #pragma unroll
            for (int u = tid; u < 32 * 128; u += 256) {
                int cc = u >> 7, pp = u & 127;
                outp[((size_t)b * CD + bn + s4 * 32 + cc) * HWD + p0 + pp] = sT[cc * 129 + pp];
            }
        }
        return;
    }

    #pragma unroll
    for (int mi = 0; mi < 4; mi++) {
        #pragma unroll
        for (int half = 0; half < 2; half++) {
            int m = bm + wm + mi * 16 + (lane >> 2) + half * 8;
            #pragma unroll
            for (int ni = 0; ni < 4; ni++) {
                int n = bn + wn + ni * 8 + (lane & 3) * 2;
                float2 bv = *(const float2*)(bias + n);
                float f0 = acc[mi][ni][half * 2 + 0] + bv.x;
                float f1 = acc[mi][ni][half * 2 + 1] + bv.y;
                if (EPI == 1) { f0 = gelu_exact(f0); f1 = gelu_exact(f1); }
                if (EPI == 2) {
                    float2 rv = *(const float2*)(res + (size_t)m * N + n);
                    *(float2*)((float*)Cout + (size_t)m * N + n) =
                        make_float2(f0 + rv.x, f1 + rv.y);
                } else {
                    *(__nv_bfloat162*)((__nv_bfloat16*)Cout + (size_t)m * N + n) =
                        __floats2bfloat162_rn(f0, f1);
                }
            }
        }
    }
}

// ---------------- windowed attention: one warp per (window, head) -------------
// 8 warps/block, per-warp smem q/k/v (16 x AQ bf16 each) + 16x17 f32 scores.
// No block syncs; occupancy-driven latency hiding. Same arithmetic order as before.
__global__ void __launch_bounds__(256) attn_kernel(const __nv_bfloat16* __restrict__ qkv,
        const float* __restrict__ rpb, __nv_bfloat16* __restrict__ O) {
    __shared__ __nv_bfloat16 sq[8][3][16 * AQ];   // 8 * 3 * 576 * 2 = 27648 B
    __shared__ float sS[8][16 * 17];              // 8704 B
    const int wid = threadIdx.x >> 5, lane = threadIdx.x & 31;
    const int g = blockIdx.x * 8 + wid;           // global (window, head) id
    const int w = g >> 4, h = g & 15;
    const int b = w >> 6, wi = w & 63, wh = wi >> 3, ww = wi & 7;
    const int base = (b * 32 + wh * 4) * 32 + ww * 4;

    // load this head's q,k,v: 16 tokens x 32 bf16 each. 2 rows per pass (64 B rows).
    #pragma unroll
    for (int pass = 0; pass < 8; pass++) {
        int i = pass * 2 + (lane >> 4);
        int t = base + (i >> 2) * 32 + (i & 3);
        const uint32_t* src = (const uint32_t*)(qkv + (size_t)t * 1536 + h * HD);
        int wd = lane & 15;
        #pragma unroll
        for (int a = 0; a < 3; a++)               // q @ +0, k @ +512, v @ +1024 bf16
            ((uint32_t*)&sq[wid][a][i * AQ])[wd] = src[a * 256 + wd];
    }
    __syncwarp();

    float* Sh = sS[wid];
    const float scale = 0.17677669529663689f;
    #pragma unroll
    for (int e = 0; e < 8; e++) {
        int idx = lane * 8 + e;
        int i = idx >> 4, j = idx & 15;
        const __nv_bfloat162* qp = (const __nv_bfloat162*)&sq[wid][0][i * AQ];
        const __nv_bfloat162* kp = (const __nv_bfloat162*)&sq[wid][1][j * AQ];
        float acc = 0.f;
        #pragma unroll
        for (int d = 0; d < 16; d++) {
            float2 qa = __bfloat1622float2(qp[d]);
            float2 kb = __bfloat1622float2(kp[d]);
            acc += qa.x * kb.x + qa.y * kb.y;
        }
        int ri = i >> 2, ci = i & 3, rj = j >> 2, cj = j & 3;
        int bidx = (ri - rj + 3) * 7 + (ci - cj + 3);
        Sh[i * 17 + j] = acc * scale + rpb[bidx * NHEAD + h];
    }
    __syncwarp();
    if (lane < 16) {
        float* row = Sh + lane * 17;
        float m = row[0];
        #pragma unroll
        for (int j = 1; j < 16; j++) m = fmaxf(m, row[j]);
        float s = 0.f;
        #pragma unroll
        for (int j = 0; j < 16; j++) { float e = __expf(row[j] - m); row[j] = e; s += e; }
        float inv = 1.f / s;
        #pragma unroll
        for (int j = 0; j < 16; j++) row[j] *= inv;
    }
    __syncwarp();
    #pragma unroll
    for (int i = 0; i < 16; i++) {
        float acc = 0.f;
        #pragma unroll
        for (int j = 0; j < 16; j++)
            acc += Sh[i * 17 + j] * __bfloat162float(sq[wid][2][j * AQ + lane]);
        int t = base + (i >> 2) * 32 + (i & 3);
        O[(size_t)t * CD + h * HD + lane] = __float2bfloat16(acc);
    }
}

// ---------------- launch ----------------
extern "C" void kernel_launch(void* const* d_in, const int* in_sizes, int n_in,
                              void* d_out, int out_size) {
    const float* x      = (const float*)d_in[0];
    const float* n1w    = (const float*)d_in[1];
    const float* n1b    = (const float*)d_in[2];
    const float* qkv_w  = (const float*)d_in[3];
    const float* qkv_b  = (const float*)d_in[4];
    const float* rpb    = (const float*)d_in[5];
    const float* proj_w = (const float*)d_in[6];
    const float* proj_b = (const float*)d_in[7];
    const float* n2w    = (const float*)d_in[8];
    const float* n2b    = (const float*)d_in[9];
    const float* w1     = (const float*)d_in[10];
    const float* b1     = (const float*)d_in[11];
    const float* w2     = (const float*)d_in[12];
    const float* b2     = (const float*)d_in[13];
    float* out = (float*)d_out;

    float *xh, *x2;
    __nv_bfloat16 *xnb, *qkvb, *attb, *yb, *h1b, *wqkv, *wprj, *w1b, *w2b;
    cudaGetSymbolAddress((void**)&xh,   g_xh);
    cudaGetSymbolAddress((void**)&x2,   g_x2);
    cudaGetSymbolAddress((void**)&xnb,  g_xnb);
    cudaGetSymbolAddress((void**)&qkvb, g_qkvb);
    cudaGetSymbolAddress((void**)&attb, g_attb);
    cudaGetSymbolAddress((void**)&yb,   g_yb);
    cudaGetSymbolAddress((void**)&h1b,  g_h1b);
    cudaGetSymbolAddress((void**)&wqkv, g_wqkv);
    cudaGetSymbolAddress((void**)&wprj, g_wprj);
    cudaGetSymbolAddress((void**)&w1b,  g_w1);
    cudaGetSymbolAddress((void**)&w2b,  g_w2);

    cudaFuncSetAttribute(gemm_mma<0>, cudaFuncAttributeMaxDynamicSharedMemorySize, GSMEM);
    cudaFuncSetAttribute(gemm_mma<1>, cudaFuncAttributeMaxDynamicSharedMemorySize, GSMEM);
    cudaFuncSetAttribute(gemm_mma<2>, cudaFuncAttributeMaxDynamicSharedMemorySize, GSMEM);
    cudaFuncSetAttribute(gemm_mma<3>, cudaFuncAttributeMaxDynamicSharedMemorySize, GSMEM);

    dim3 tb(32, 8);
    // Launch order puts the QKV GEMM at capture index 3 so ncu finally profiles it.
    transpose_in<<<dim3(32, 16, 32), tb>>>(x, xh);                                   // 0
    wcvt<<<(1536 * 512 + 255) / 256, 256>>>(qkv_w, wqkv, 1536 * 512);                // 1
    ln_kernel<<<TOK / 8, 256>>>(xh, n1w, n1b, xnb);                                  // 2
    gemm_mma<0><<<dim3(12, 256), 256, GSMEM>>>(xnb, wqkv, qkv_b, nullptr, qkvb,      // 3 <- ncu
                                               TOK, 1536, 512);
    wcvt<<<(512  * 512 + 255) / 256, 256>>>(proj_w, wprj, 512 * 512);                // 4
    wcvt<<<(2048 * 512 + 255) / 256, 256>>>(w1,     w1b,  2048 * 512);               // 5
    wcvt<<<(512 * 2048 + 255) / 256, 256>>>(w2,     w2b,  512 * 2048);               // 6
    attn_kernel<<<NWIN * NHEAD / 8, 256>>>(qkvb, rpb, attb);                         // 7
    gemm_mma<2><<<dim3(4, 256), 256, GSMEM>>>(attb, wprj, proj_b, xh, x2, TOK, 512, 512);
    ln_kernel<<<TOK / 8, 256>>>(x2, n2w, n2b, yb);
    gemm_mma<1><<<dim3(16, 256), 256, GSMEM>>>(yb, w1b, b1, nullptr, h1b, TOK, 2048, 512);
    gemm_mma<3><<<dim3(4, 256), 256, GSMEM>>>(h1b, w2b, b2, x2, out, TOK, 512, 2048);
}

// round 15
// speedup vs baseline: 1.1262x; 1.0854x over previous
#include <cuda_runtime.h>
#include <cuda_bf16.h>
#include <math.h>
#include <stdint.h>

// ---------------- problem constants ----------------
#define TOK   32768      // B*H*W tokens
#define CD    512        // channels
#define HWD   1024       // H*W per batch
#define NHEAD 16
#define HD    32
#define NWIN  2048       // B * 64 windows
#define SSTR2 72         // gemm smem row stride bf16 (64 data + 8 pad) = 144 B
#define ATILE 18432      // bytes per A (or B) tile in one stage: 128 * 72 * 2
#define STAGEB2 36864    // bytes per stage (A + B)
#define GSMEM2  (2 * STAGEB2)   // 73728 B dynamic smem
#define AQ    36         // attn per-warp qkv row stride in bf16 (72 B)

// ---------------- scratch (__device__ globals, no allocation) ----------------
__device__ __align__(16) float         g_xh  [TOK * CD];
__device__ __align__(16) float         g_x2  [TOK * CD];
__device__ __align__(16) __nv_bfloat16 g_xnb [TOK * CD];
__device__ __align__(16) __nv_bfloat16 g_qkvb[TOK * 1536];
__device__ __align__(16) __nv_bfloat16 g_attb[TOK * CD];
__device__ __align__(16) __nv_bfloat16 g_yb  [TOK * CD];
__device__ __align__(16) __nv_bfloat16 g_h1b [TOK * 2048];
__device__ __align__(16) __nv_bfloat16 g_wqkv[1536 * 512];
__device__ __align__(16) __nv_bfloat16 g_wprj[512 * 512];
__device__ __align__(16) __nv_bfloat16 g_w1  [2048 * 512];
__device__ __align__(16) __nv_bfloat16 g_w2  [512 * 2048];

// ---------------- PTX helpers (portable sm_80+ only) ----------------
__device__ __forceinline__ uint32_t smem_u32(const void* p) {
    uint32_t a;
    asm("{ .reg .u64 t; cvta.to.shared.u64 t, %1; cvt.u32.u64 %0, t; }" : "=r"(a) : "l"(p));
    return a;
}
__device__ __forceinline__ void ldsm_x4(uint32_t* r, uint32_t addr) {
    asm volatile("ldmatrix.sync.aligned.m8n8.x4.shared.b16 {%0,%1,%2,%3}, [%4];"
        : "=r"(r[0]), "=r"(r[1]), "=r"(r[2]), "=r"(r[3]) : "r"(addr));
}
__device__ __forceinline__ void mma_bf16(float* d, const uint32_t* a, const uint32_t* b) {
    asm volatile("mma.sync.aligned.m16n8k16.row.col.f32.bf16.bf16.f32 "
        "{%0,%1,%2,%3}, {%4,%5,%6,%7}, {%8,%9}, {%0,%1,%2,%3};"
        : "+f"(d[0]), "+f"(d[1]), "+f"(d[2]), "+f"(d[3])
        : "r"(a[0]), "r"(a[1]), "r"(a[2]), "r"(a[3]), "r"(b[0]), "r"(b[1]));
}
__device__ __forceinline__ void cp_async16(uint32_t dst, const void* src) {
    asm volatile("cp.async.cg.shared.global [%0], [%1], 16;" :: "r"(dst), "l"(src));
}
#define CP_COMMIT() asm volatile("cp.async.commit_group;" ::: "memory")
#define CP_WAIT(n)  asm volatile("cp.async.wait_group %0;" :: "n"(n) : "memory")

// ---------------- transpose in ----------------
__global__ void transpose_in(const float* __restrict__ x, float* __restrict__ xh) {
    __shared__ float tile[32][33];
    int b = blockIdx.z, c0 = blockIdx.y * 32, p0 = blockIdx.x * 32;
    int tx = threadIdx.x, ty = threadIdx.y;
    #pragma unroll
    for (int i = 0; i < 32; i += 8)
        tile[ty + i][tx] = x[((size_t)b * CD + c0 + ty + i) * HWD + p0 + tx];
    __syncthreads();
    #pragma unroll
    for (int i = 0; i < 32; i += 8)
        xh[((size_t)b * HWD + p0 + ty + i) * CD + c0 + tx] = tile[tx][ty + i];
}

// ---------------- weight fp32 -> bf16 ----------------
__global__ void wcvt(const float* __restrict__ s, __nv_bfloat16* __restrict__ d, int n) {
    int i = blockIdx.x * 256 + threadIdx.x;
    if (i < n) d[i] = __float2bfloat16(s[i]);
}

// ---------------- LayerNorm (fp32 in -> bf16 out) ----------------
__global__ void __launch_bounds__(256) ln_kernel(const float* __restrict__ in,
        const float* __restrict__ w, const float* __restrict__ b,
        __nv_bfloat16* __restrict__ out) {
    int row  = blockIdx.x * 8 + (threadIdx.x >> 5);
    int lane = threadIdx.x & 31;
    const float4* p = (const float4*)(in + (size_t)row * CD);
    float4 v[4];
    float s = 0.f, s2 = 0.f;
    #pragma unroll
    for (int j = 0; j < 4; j++) {
        v[j] = p[lane + 32 * j];
        s  += v[j].x + v[j].y + v[j].z + v[j].w;
        s2 += v[j].x * v[j].x + v[j].y * v[j].y + v[j].z * v[j].z + v[j].w * v[j].w;
    }
    #pragma unroll
    for (int o = 16; o > 0; o >>= 1) {
        s  += __shfl_xor_sync(0xffffffffu, s,  o);
        s2 += __shfl_xor_sync(0xffffffffu, s2, o);
    }
    float mean = s * (1.f / CD);
    float var  = s2 * (1.f / CD) - mean * mean;
    float rstd = rsqrtf(var + 1e-5f);
    __nv_bfloat16* q = out + (size_t)row * CD;
    const float4* wp = (const float4*)w;
    const float4* bp = (const float4*)b;
    #pragma unroll
    for (int j = 0; j < 4; j++) {
        int c4 = lane + 32 * j;
        float4 wv = wp[c4], bv = bp[c4], x = v[j];
        float ox = (x.x - mean) * rstd * wv.x + bv.x;
        float oy = (x.y - mean) * rstd * wv.y + bv.y;
        float oz = (x.z - mean) * rstd * wv.z + bv.z;
        float ow = (x.w - mean) * rstd * wv.w + bv.w;
        *(__nv_bfloat162*)(q + c4 * 4)     = __floats2bfloat162_rn(ox, oy);
        *(__nv_bfloat162*)(q + c4 * 4 + 2) = __floats2bfloat162_rn(oz, ow);
    }
}

// ---------------- mma.sync bf16 GEMM: K-chunk 64, 2 stages, 1 sync/chunk -----
// Block 128x128, 8 warps (2x4), warp tile 64x32.
// EPI: 0 bf16 out; 1 gelu->bf16; 2 +fp32 residual->fp32; 3 +fp32 residual -> [B,C,HW] fp32.
__device__ __forceinline__ float gelu_exact(float v) {
    return 0.5f * v * (1.f + erff(v * 0.70710678118654752f));
}

template <int EPI>
__global__ void __launch_bounds__(256, 2) gemm_mma(
        const __nv_bfloat16* __restrict__ A, const __nv_bfloat16* __restrict__ Wt,
        const float* __restrict__ bias, const float* __restrict__ res,
        void* __restrict__ Cout, int M, int N, int K) {
    extern __shared__ __align__(16) char smem[];
    const int tid = threadIdx.x, wid = tid >> 5, lane = tid & 31;
    const int bm = blockIdx.y * 128, bn = blockIdx.x * 128;
    const int wm = (wid >> 2) * 64, wn = (wid & 3) * 32;
    const uint32_t sb = smem_u32(smem);

    float acc[4][4][4];
    #pragma unroll
    for (int i = 0; i < 4; i++)
        #pragma unroll
        for (int j = 0; j < 4; j++)
            #pragma unroll
            for (int q = 0; q < 4; q++) acc[i][j][q] = 0.f;

    const int NC = K >> 6;   // K-chunks of 64; K is 512 or 2048

    // one stage = A[128x64] + B[128x64], 16B chunks: 1024 + 1024, 8 per thread
    auto issue = [&](int stg, int k0) {
        uint32_t base = sb + stg * STAGEB2;
        #pragma unroll
        for (int i = 0; i < 8; i++) {
            int u = tid + i * 256;
            if (u < 1024) {
                int r = u >> 3, q = u & 7;
                cp_async16(base + (uint32_t)(r * SSTR2 + q * 8) * 2,
                           A + (size_t)(bm + r) * K + k0 + q * 8);
            } else {
                int v = u - 1024, r = v >> 3, q = v & 7;
                cp_async16(base + ATILE + (uint32_t)(r * SSTR2 + q * 8) * 2,
                           Wt + (size_t)(bn + r) * K + k0 + q * 8);
            }
        }
        CP_COMMIT();
    };

    issue(0, 0);
    for (int c = 0; c < NC; c++) {
        CP_WAIT(0);                // drain the single pending group (chunk c)
        __syncthreads();           // all threads done reading the buffer we refill next
        if (c + 1 < NC) issue((c + 1) & 1, (c + 1) * 64);
        const uint32_t Ab = sb + (c & 1) * STAGEB2;
        const uint32_t Bb = Ab + ATILE;
        #pragma unroll
        for (int kk = 0; kk < 4; kk++) {
            uint32_t a[4][4], b[4][2];
            #pragma unroll
            for (int mi = 0; mi < 4; mi++) {
                uint32_t row = wm + mi * 16 + (lane & 15);
                uint32_t kb  = kk * 32 + (lane >> 4) * 16;       // bytes within 128B row
                ldsm_x4(a[mi], Ab + row * (SSTR2 * 2) + kb);
            }
            #pragma unroll
            for (int nh = 0; nh < 2; nh++) {
                uint32_t r4[4];
                uint32_t nrow = wn + nh * 16 + (lane & 7) + ((lane >> 4) << 3);
                uint32_t kb   = kk * 32 + ((lane >> 3) & 1) * 16;
                ldsm_x4(r4, Bb + nrow * (SSTR2 * 2) + kb);
                b[nh * 2 + 0][0] = r4[0]; b[nh * 2 + 0][1] = r4[1];
                b[nh * 2 + 1][0] = r4[2]; b[nh * 2 + 1][1] = r4[3];
            }
            #pragma unroll
            for (int mi = 0; mi < 4; mi++)
                #pragma unroll
                for (int ni = 0; ni < 4; ni++)
                    mma_bf16(acc[mi][ni], a[mi], b[ni]);
        }
        // no trailing sync: next iteration's start-of-chunk sync provides ordering
    }
    __syncthreads();   // protect smem reuse in EPI=3 epilogue

    if (EPI == 3) {
        float* sT = (float*)smem;
        const int b  = bm >> 10;
        const int p0 = bm & 1023;
        float* outp = (float*)Cout;
        #pragma unroll 1
        for (int s4 = 0; s4 < 4; s4++) {
            __syncthreads();
            if ((wid & 3) == s4) {
                #pragma unroll
                for (int mi = 0; mi < 4; mi++)
                    #pragma unroll
                    for (int half = 0; half < 2; half++) {
                        int ml = wm + mi * 16 + (lane >> 2) + half * 8;
                        #pragma unroll
                        for (int ni = 0; ni < 4; ni++) {
                            int nl = ni * 8 + (lane & 3) * 2;
                            int ng = bn + s4 * 32 + nl;
                            float2 bv = *(const float2*)(bias + ng);
                            float2 rv = *(const float2*)(res + (size_t)(bm + ml) * N + ng);
                            sT[nl * 129 + ml]       = acc[mi][ni][half * 2 + 0] + bv.x + rv.x;
                            sT[(nl + 1) * 129 + ml] = acc[mi][ni][half * 2 + 1] + bv.y + rv.y;
                        }
                    }
            }
            __syncthreads();
            #pragma unroll
            for (int u = tid; u < 32 * 128; u += 256) {
                int cc = u >> 7, pp = u & 127;
                outp[((size_t)b * CD + bn + s4 * 32 + cc) * HWD + p0 + pp] = sT[cc * 129 + pp];
            }
        }
        return;
    }

    #pragma unroll
    for (int mi = 0; mi < 4; mi++) {
        #pragma unroll
        for (int half = 0; half < 2; half++) {
            int m = bm + wm + mi * 16 + (lane >> 2) + half * 8;
            #pragma unroll
            for (int ni = 0; ni < 4; ni++) {
                int n = bn + wn + ni * 8 + (lane & 3) * 2;
                float2 bv = *(const float2*)(bias + n);
                float f0 = acc[mi][ni][half * 2 + 0] + bv.x;
                float f1 = acc[mi][ni][half * 2 + 1] + bv.y;
                if (EPI == 1) { f0 = gelu_exact(f0); f1 = gelu_exact(f1); }
                if (EPI == 2) {
                    float2 rv = *(const float2*)(res + (size_t)m * N + n);
                    *(float2*)((float*)Cout + (size_t)m * N + n) =
                        make_float2(f0 + rv.x, f1 + rv.y);
                } else {
                    *(__nv_bfloat162*)((__nv_bfloat16*)Cout + (size_t)m * N + n) =
                        __floats2bfloat162_rn(f0, f1);
                }
            }
        }
    }
}

// ---------------- windowed attention: one warp per (window, head) -------------
__global__ void __launch_bounds__(256) attn_kernel(const __nv_bfloat16* __restrict__ qkv,
        const float* __restrict__ rpb, __nv_bfloat16* __restrict__ O) {
    __shared__ __nv_bfloat16 sq[8][3][16 * AQ];
    __shared__ float sS[8][16 * 17];
    const int wid = threadIdx.x >> 5, lane = threadIdx.x & 31;
    const int g = blockIdx.x * 8 + wid;
    const int w = g >> 4, h = g & 15;
    const int b = w >> 6, wi = w & 63, wh = wi >> 3, ww = wi & 7;
    const int base = (b * 32 + wh * 4) * 32 + ww * 4;

    #pragma unroll
    for (int pass = 0; pass < 8; pass++) {
        int i = pass * 2 + (lane >> 4);
        int t = base + (i >> 2) * 32 + (i & 3);
        const uint32_t* src = (const uint32_t*)(qkv + (size_t)t * 1536 + h * HD);
        int wd = lane & 15;
        #pragma unroll
        for (int a = 0; a < 3; a++)
            ((uint32_t*)&sq[wid][a][i * AQ])[wd] = src[a * 256 + wd];
    }
    __syncwarp();

    float* Sh = sS[wid];
    const float scale = 0.17677669529663689f;
    #pragma unroll
    for (int e = 0; e < 8; e++) {
        int idx = lane * 8 + e;
        int i = idx >> 4, j = idx & 15;
        const __nv_bfloat162* qp = (const __nv_bfloat162*)&sq[wid][0][i * AQ];
        const __nv_bfloat162* kp = (const __nv_bfloat162*)&sq[wid][1][j * AQ];
        float acc = 0.f;
        #pragma unroll
        for (int d = 0; d < 16; d++) {
            float2 qa = __bfloat1622float2(qp[d]);
            float2 kb = __bfloat1622float2(kp[d]);
            acc += qa.x * kb.x + qa.y * kb.y;
        }
        int ri = i >> 2, ci = i & 3, rj = j >> 2, cj = j & 3;
        int bidx = (ri - rj + 3) * 7 + (ci - cj + 3);
        Sh[i * 17 + j] = acc * scale + rpb[bidx * NHEAD + h];
    }
    __syncwarp();
    if (lane < 16) {
        float* row = Sh + lane * 17;
        float m = row[0];
        #pragma unroll
        for (int j = 1; j < 16; j++) m = fmaxf(m, row[j]);
        float s = 0.f;
        #pragma unroll
        for (int j = 0; j < 16; j++) { float e = __expf(row[j] - m); row[j] = e; s += e; }
        float inv = 1.f / s;
        #pragma unroll
        for (int j = 0; j < 16; j++) row[j] *= inv;
    }
    __syncwarp();
    #pragma unroll
    for (int i = 0; i < 16; i++) {
        float acc = 0.f;
        #pragma unroll
        for (int j = 0; j < 16; j++)
            acc += Sh[i * 17 + j] * __bfloat162float(sq[wid][2][j * AQ + lane]);
        int t = base + (i >> 2) * 32 + (i & 3);
        O[(size_t)t * CD + h * HD + lane] = __float2bfloat16(acc);
    }
}

// ---------------- launch ----------------
extern "C" void kernel_launch(void* const* d_in, const int* in_sizes, int n_in,
                              void* d_out, int out_size) {
    const float* x      = (const float*)d_in[0];
    const float* n1w    = (const float*)d_in[1];
    const float* n1b    = (const float*)d_in[2];
    const float* qkv_w  = (const float*)d_in[3];
    const float* qkv_b  = (const float*)d_in[4];
    const float* rpb    = (const float*)d_in[5];
    const float* proj_w = (const float*)d_in[6];
    const float* proj_b = (const float*)d_in[7];
    const float* n2w    = (const float*)d_in[8];
    const float* n2b    = (const float*)d_in[9];
    const float* w1     = (const float*)d_in[10];
    const float* b1     = (const float*)d_in[11];
    const float* w2     = (const float*)d_in[12];
    const float* b2     = (const float*)d_in[13];
    float* out = (float*)d_out;

    float *xh, *x2;
    __nv_bfloat16 *xnb, *qkvb, *attb, *yb, *h1b, *wqkv, *wprj, *w1b, *w2b;
    cudaGetSymbolAddress((void**)&xh,   g_xh);
    cudaGetSymbolAddress((void**)&x2,   g_x2);
    cudaGetSymbolAddress((void**)&xnb,  g_xnb);
    cudaGetSymbolAddress((void**)&qkvb, g_qkvb);
    cudaGetSymbolAddress((void**)&attb, g_attb);
    cudaGetSymbolAddress((void**)&yb,   g_yb);
    cudaGetSymbolAddress((void**)&h1b,  g_h1b);
    cudaGetSymbolAddress((void**)&wqkv, g_wqkv);
    cudaGetSymbolAddress((void**)&wprj, g_wprj);
    cudaGetSymbolAddress((void**)&w1b,  g_w1);
    cudaGetSymbolAddress((void**)&w2b,  g_w2);

    cudaFuncSetAttribute(gemm_mma<0>, cudaFuncAttributeMaxDynamicSharedMemorySize, GSMEM2);
    cudaFuncSetAttribute(gemm_mma<1>, cudaFuncAttributeMaxDynamicSharedMemorySize, GSMEM2);
    cudaFuncSetAttribute(gemm_mma<2>, cudaFuncAttributeMaxDynamicSharedMemorySize, GSMEM2);
    cudaFuncSetAttribute(gemm_mma<3>, cudaFuncAttributeMaxDynamicSharedMemorySize, GSMEM2);

    dim3 tb(32, 8);
    // QKV GEMM at capture index 3 for ncu.
    transpose_in<<<dim3(32, 16, 32), tb>>>(x, xh);                                   // 0
    wcvt<<<(1536 * 512 + 255) / 256, 256>>>(qkv_w, wqkv, 1536 * 512);                // 1
    ln_kernel<<<TOK / 8, 256>>>(xh, n1w, n1b, xnb);                                  // 2
    gemm_mma<0><<<dim3(12, 256), 256, GSMEM2>>>(xnb, wqkv, qkv_b, nullptr, qkvb,     // 3 <- ncu
                                                TOK, 1536, 512);
    wcvt<<<(512  * 512 + 255) / 256, 256>>>(proj_w, wprj, 512 * 512);                // 4
    wcvt<<<(2048 * 512 + 255) / 256, 256>>>(w1,     w1b,  2048 * 512);               // 5
    wcvt<<<(512 * 2048 + 255) / 256, 256>>>(w2,     w2b,  512 * 2048);               // 6
    attn_kernel<<<NWIN * NHEAD / 8, 256>>>(qkvb, rpb, attb);                         // 7
    gemm_mma<2><<<dim3(4, 256), 256, GSMEM2>>>(attb, wprj, proj_b, xh, x2, TOK, 512, 512);
    ln_kernel<<<TOK / 8, 256>>>(x2, n2w, n2b, yb);
    gemm_mma<1><<<dim3(16, 256), 256, GSMEM2>>>(yb, w1b, b1, nullptr, h1b, TOK, 2048, 512);
    gemm_mma<3><<<dim3(4, 256), 256, GSMEM2>>>(h1b, w2b, b2, x2, out, TOK, 512, 2048);
}